// round 4
// baseline (speedup 1.0000x reference)
#include <cuda_runtime.h>
#include <math.h>
#include <stdint.h>

typedef unsigned long long ull;

#define T_STEPS 1024
#define BATCH   64
#define IN_DIM  512
#define H_DIM   1024

#define NCTA         128
#define SCAN_THREADS 512
#define NGROUPS      4          // k-split groups (128 threads each)
#define COLS_PER_CTA 8          // 128 CTAs * 8 cols = 1024 = H_DIM
#define KCHUNK       256        // k-chunk staged in smem per double-buffer slot
#define NCHUNKS      (H_DIM / KCHUNK)   // 4
#define KPG          (KCHUNK / NGROUPS) // 64 k per group per chunk
#define WPK_PITCH    1030       // ull pitch per column row (bank-conflict-free)

// Transposed hidden state, double-buffered: g_ht[p][col*BATCH + row]
__device__ float g_ht[2][H_DIM * BATCH];
// Grid barrier: monotonic arrival counter + separately-polled epoch word
__device__ ull g_count = 0ULL;
__device__ ull g_epoch = 0ULL;

// ---------------------------------------------------------------------------
// packed f32x2 helpers (Blackwell sm_103a)
// ---------------------------------------------------------------------------
__device__ __forceinline__ ull pack2(float a, float b)
{
    ull r; asm("mov.b64 %0, {%1, %2};" : "=l"(r) : "f"(a), "f"(b)); return r;
}
__device__ __forceinline__ void unpack2(ull v, float& a, float& b)
{
    asm("mov.b64 {%0, %1}, %2;" : "=f"(a), "=f"(b) : "l"(v));
}
__device__ __forceinline__ void fma2(ull& acc, ull a, ull b)
{
    asm("fma.rn.f32x2 %0, %1, %2, %0;" : "+l"(acc) : "l"(a), "l"(b));
}
__device__ __forceinline__ ull add2(ull a, ull b)
{
    ull r; asm("add.rn.f32x2 %0, %1, %2;" : "=l"(r) : "l"(a), "l"(b)); return r;
}

// ---------------------------------------------------------------------------
// Kernel 1: xproj = x @ Wx + b  (out doubles as xproj buffer)
// M=65536, K=512, N=1024. BM=64, BN=64, BK=16; 256 threads; 4x4 microtile,
// accumulators held as packed f32x2 pairs -> 8 FFMA2 per k per thread.
// ---------------------------------------------------------------------------
__global__ void __launch_bounds__(256) xproj_kernel(
    const float* __restrict__ x,
    const float* __restrict__ W,     // full (IN+H, H); Wx = rows [0,512)
    const float* __restrict__ bias,
    float* __restrict__ out)
{
    __shared__ float As[16][64];     // [k][m]
    __shared__ float Bs[16][64];     // [k][n]

    const int tid  = threadIdx.x;
    const int row0 = blockIdx.y * 64;
    const int col0 = blockIdx.x * 64;

    const int ty = tid >> 4;               // 0..15 (row group)
    const int tx = tid & 15;               // 0..15 (col group)

    const int lmA = tid >> 2;              // 0..63
    const int lkA = (tid & 3) << 2;        // 0,4,8,12
    const int lkB = tid >> 4;              // 0..15
    const int lnB = (tid & 15) << 2;       // 0..60

    ull acc01[4], acc23[4];
#pragma unroll
    for (int i = 0; i < 4; ++i) { acc01[i] = 0ULL; acc23[i] = 0ULL; }

    const float* xg = x + (size_t)(row0 + lmA) * IN_DIM + lkA;

    for (int k0 = 0; k0 < IN_DIM; k0 += 16) {
        float4 av = *(const float4*)(xg + k0);
        As[lkA + 0][lmA] = av.x;
        As[lkA + 1][lmA] = av.y;
        As[lkA + 2][lmA] = av.z;
        As[lkA + 3][lmA] = av.w;

        float4 bv = *(const float4*)(W + (size_t)(k0 + lkB) * H_DIM + col0 + lnB);
        *(float4*)&Bs[lkB][lnB] = bv;

        __syncthreads();
#pragma unroll
        for (int k = 0; k < 16; ++k) {
            float4 a = *(const float4*)&As[k][ty << 2];
            ulonglong2 b = *(const ulonglong2*)&Bs[k][tx << 2];  // (b0,b1),(b2,b3)
            ull ax = pack2(a.x, a.x);
            ull ay = pack2(a.y, a.y);
            ull az = pack2(a.z, a.z);
            ull aw = pack2(a.w, a.w);
            fma2(acc01[0], ax, b.x); fma2(acc23[0], ax, b.y);
            fma2(acc01[1], ay, b.x); fma2(acc23[1], ay, b.y);
            fma2(acc01[2], az, b.x); fma2(acc23[2], az, b.y);
            fma2(acc01[3], aw, b.x); fma2(acc23[3], aw, b.y);
        }
        __syncthreads();
    }

    float4 bb = *(const float4*)(bias + col0 + (tx << 2));
#pragma unroll
    for (int i = 0; i < 4; ++i) {
        float s0, s1, s2, s3;
        unpack2(acc01[i], s0, s1);
        unpack2(acc23[i], s2, s3);
        float4 o;
        o.x = s0 + bb.x;
        o.y = s1 + bb.y;
        o.z = s2 + bb.z;
        o.w = s3 + bb.w;
        *(float4*)(out + (size_t)(row0 + (ty << 2) + i) * H_DIM + col0 + (tx << 2)) = o;
    }
}

// ---------------------------------------------------------------------------
// Scan kernel helpers
// ---------------------------------------------------------------------------
__device__ __forceinline__ void cp_async16(float* sdst, const float* gsrc)
{
    unsigned sa = (unsigned)__cvta_generic_to_shared(sdst);
    asm volatile("cp.async.cg.shared.global [%0], [%1], 16;\n" :: "r"(sa), "l"(gsrc));
}

__device__ __forceinline__ void stage_chunk(const float* gsrc, float* sdst, int tid)
{
    // KCHUNK*BATCH = 16384 floats = 4096 float4s; 512 threads * 8 each
#pragma unroll
    for (int i = 0; i < 8; ++i) {
        int idx = tid + i * SCAN_THREADS;   // 0..4095
        cp_async16(sdst + idx * 4, gsrc + idx * 4);
    }
}

// Arrivals bump a counter; the last arriver release-publishes the new epoch
// to a separate word. Waiters acquire-poll only the epoch word, so read
// traffic never contends with the RMWs on the counter.
__device__ __forceinline__ void grid_barrier()
{
    __syncthreads();
    if (threadIdx.x == 0) {
        __threadfence();
        ull old = atomicAdd(&g_count, 1ULL);
        ull target = (old / NCTA + 1ULL) * (ull)NCTA;
        if (old + 1ULL == target) {
            asm volatile("st.release.gpu.global.u64 [%0], %1;" :: "l"(&g_epoch), "l"(target));
        } else {
            ull cur;
            do {
                asm volatile("ld.acquire.gpu.global.u64 %0, [%1];" : "=l"(cur) : "l"(&g_epoch));
            } while (cur < target);
        }
    }
    __syncthreads();
}

// ---------------------------------------------------------------------------
// Kernel 2: persistent recurrent scan.
// 128 CTAs (single wave) x 512 threads (16 warps, 4 per SMSP).
// CTA owns 8 output columns. Wh slice pre-packed (w,w) as f32x2 in smem,
// layout [c][k] pitch 1030 ull -> conflict-free LDS.128.
// h_prev staged through smem in 4 chunks of 256 k, cp.async double-buffered.
// 4 thread groups split each chunk's K four ways; 3 partials reduced through
// smem (reuses hbuf0 - last chunk computes from hbuf1). Inner math is packed
// fma.rn.f32x2. Prologue transposes h's own columns into g_ht[0].
// ---------------------------------------------------------------------------
__global__ void __launch_bounds__(SCAN_THREADS) scan_kernel(
    const float* __restrict__ hinit,  // initial h (B,H)
    const float* __restrict__ W,      // Wh = rows [512, 1536)
    float* __restrict__ out)
{
    extern __shared__ float smem[];
    ull*   wpk   = (ull*)smem;                          // 8 x 1030 ull = 65920 B
    float* hbuf0 = smem + 2 * 8 * WPK_PITCH;            // [256][64] floats (64 KB)
    float* hbuf1 = hbuf0 + KCHUNK * BATCH;              // (64 KB)
    ulonglong2* red = (ulonglong2*)hbuf0;               // [3][128], reused

    const int tid   = threadIdx.x;
    const int lid   = tid & 127;              // lane within group
    const int grp   = tid >> 7;               // 0..3 (k-split group)
    const int col0  = blockIdx.x * COLS_PER_CTA;
    const int c     = lid & 7;                 // column within CTA tile
    const int rquad = (lid >> 3) << 2;         // base row (0,4,...,60)

    // Prologue A: transpose my 8 columns of initial h into g_ht[0]
    if (tid < COLS_PER_CTA * BATCH) {          // 512 threads, 512 elements
        int cc = tid >> 6;        // 0..7
        int r  = tid & 63;        // 0..63
        g_ht[0][(col0 + cc) * BATCH + r] = hinit[r * H_DIM + col0 + cc];
    }

    // Prologue B: pre-pack resident Wh slice: wpk[cc][k] = (w, w)
    for (int i = tid; i < H_DIM * COLS_PER_CTA; i += SCAN_THREADS) {
        int cc = i >> 10;        // 0..7
        int k  = i & 1023;       // 0..1023
        float w = W[(size_t)(IN_DIM + k) * H_DIM + col0 + cc];
        wpk[cc * WPK_PITCH + k] = pack2(w, w);
    }

    // all CTAs' transposes must be visible before step 0 staging
    grid_barrier();

    // group k-offset baked into weight pointer (grp*KPG within each chunk)
    const ull* wc = wpk + c * WPK_PITCH + grp * KPG;

    const size_t out_off0 = (size_t)(rquad + 0) * H_DIM + col0 + c;
    const size_t out_off1 = (size_t)(rquad + 1) * H_DIM + col0 + c;
    const size_t out_off2 = (size_t)(rquad + 2) * H_DIM + col0 + c;
    const size_t out_off3 = (size_t)(rquad + 3) * H_DIM + col0 + c;

    // prefetch xp for step 0 (group 0 computes the epilogue)
    float xp0 = 0.f, xp1 = 0.f, xp2 = 0.f, xp3 = 0.f;
    if (grp == 0) {
        xp0 = out[out_off0];
        xp1 = out[out_off1];
        xp2 = out[out_off2];
        xp3 = out[out_off3];
    }

    for (int t = 0; t < T_STEPS; ++t) {
        const float* gh  = g_ht[t & 1];
        float*       ghn = g_ht[(t + 1) & 1];
        float*       outt = out + (size_t)t * BATCH * H_DIM;

        ull a01 = 0ULL, a23 = 0ULL;

        // stage chunk 0
        stage_chunk(gh, hbuf0, tid);
        asm volatile("cp.async.commit_group;\n" ::: "memory");

#pragma unroll
        for (int kc = 0; kc < NCHUNKS; ++kc) {
            asm volatile("cp.async.wait_group 0;\n" ::: "memory");
            __syncthreads();
            if (kc + 1 < NCHUNKS) {
                float* nbuf = ((kc + 1) & 1) ? hbuf1 : hbuf0;
                stage_chunk(gh + (size_t)(kc + 1) * KCHUNK * BATCH, nbuf, tid);
                asm volatile("cp.async.commit_group;\n" ::: "memory");
            }

            const float* buf = (kc & 1) ? hbuf1 : hbuf0;
            const float* hb  = buf + grp * KPG * BATCH + rquad;   // my K slice
            const ull*   wck = wc + kc * KCHUNK;                  // my K slice weights
#pragma unroll 4
            for (int kk = 0; kk < KPG; kk += 4) {
                ulonglong2 w01 = *(const ulonglong2*)(wck + kk);
                ulonglong2 w23 = *(const ulonglong2*)(wck + kk + 2);
                ulonglong2 h0 = *(const ulonglong2*)(hb + (kk + 0) * BATCH);
                ulonglong2 h1 = *(const ulonglong2*)(hb + (kk + 1) * BATCH);
                ulonglong2 h2 = *(const ulonglong2*)(hb + (kk + 2) * BATCH);
                ulonglong2 h3 = *(const ulonglong2*)(hb + (kk + 3) * BATCH);
                fma2(a01, h0.x, w01.x); fma2(a23, h0.y, w01.x);
                fma2(a01, h1.x, w01.y); fma2(a23, h1.y, w01.y);
                fma2(a01, h2.x, w23.x); fma2(a23, h2.y, w23.x);
                fma2(a01, h3.x, w23.y); fma2(a23, h3.y, w23.y);
            }
        }

        // cross-group reduction (red aliases hbuf0; last chunk read hbuf1)
        if (grp != 0) {
            red[(grp - 1) * 128 + lid] = make_ulonglong2(a01, a23);
        }
        __syncthreads();

        if (grp == 0) {
            ulonglong2 r1 = red[0 * 128 + lid];
            ulonglong2 r2 = red[1 * 128 + lid];
            ulonglong2 r3 = red[2 * 128 + lid];
            a01 = add2(add2(a01, r1.x), add2(r2.x, r3.x));
            a23 = add2(add2(a23, r1.y), add2(r2.y, r3.y));

            float s0, s1, s2, s3;
            unpack2(a01, s0, s1);
            unpack2(a23, s2, s3);
            float v0 = tanhf(s0 + xp0);
            float v1 = tanhf(s1 + xp1);
            float v2 = tanhf(s2 + xp2);
            float v3 = tanhf(s3 + xp3);

            // write hidden state to output history
            outt[out_off0] = v0;
            outt[out_off1] = v1;
            outt[out_off2] = v2;
            outt[out_off3] = v3;

            // transposed copy for next step's staging (contiguous float4)
            *(float4*)&ghn[(col0 + c) * BATCH + rquad] = make_float4(v0, v1, v2, v3);

            // prefetch next step's xp; DRAM latency hides under the barrier
            if (t + 1 < T_STEPS) {
                const float* outn = outt + BATCH * H_DIM;
                xp0 = outn[out_off0];
                xp1 = outn[out_off1];
                xp2 = outn[out_off2];
                xp3 = outn[out_off3];
            }
        }

        grid_barrier();
    }
}

// ---------------------------------------------------------------------------
extern "C" void kernel_launch(void* const* d_in, const int* in_sizes, int n_in,
                              void* d_out, int out_size)
{
    (void)in_sizes; (void)n_in; (void)out_size;
    const float* x = (const float*)d_in[0];
    const float* h = (const float*)d_in[1];
    const float* W = (const float*)d_in[2];
    const float* b = (const float*)d_in[3];
    float* out = (float*)d_out;

    // 1) xproj = x @ Wx + b  -> out
    dim3 grid_x(H_DIM / 64, (T_STEPS * BATCH) / 64);
    xproj_kernel<<<grid_x, 256>>>(x, W, b, out);

    // 2) persistent recurrent scan (includes h transpose prologue)
    const size_t smem_bytes = (2 * 8 * WPK_PITCH + 2 * KCHUNK * BATCH) * sizeof(float);
    static int smem_set = 0;
    if (!smem_set) {
        cudaFuncSetAttribute(scan_kernel, cudaFuncAttributeMaxDynamicSharedMemorySize,
                             (int)smem_bytes);
        smem_set = 1;
    }
    scan_kernel<<<NCTA, SCAN_THREADS, smem_bytes>>>(h, W, out);
}

// round 5
// speedup vs baseline: 2.0377x; 2.0377x over previous
#include <cuda_runtime.h>
#include <math.h>
#include <stdint.h>

typedef unsigned long long ull;

#define T_STEPS 1024
#define BATCH   64
#define IN_DIM  512
#define H_DIM   1024

#define NCTA         128
#define SCAN_THREADS 256
#define COLS_PER_CTA 8          // 128 CTAs * 8 cols = 1024
#define KCHUNK       256        // k-chunk staged in smem per double-buffer slot
#define NCHUNKS      (H_DIM / KCHUNK)   // 4
#define KSLICE       32         // k per warp per chunk (8 warps * 32 = 256)
#define WPK_PITCH    1030       // ull pitch per column (bank-stagger)

// Transposed hidden state, double-buffered: g_ht[p][col*BATCH + row]
__device__ float g_ht[2][H_DIM * BATCH];
// Grid barrier: monotonic arrival counter + separately-polled epoch word
__device__ ull g_count = 0ULL;
__device__ ull g_epoch = 0ULL;

// ---------------------------------------------------------------------------
// packed f32x2 helpers (Blackwell sm_103a)
// ---------------------------------------------------------------------------
__device__ __forceinline__ ull pack2(float a, float b)
{
    ull r; asm("mov.b64 %0, {%1, %2};" : "=l"(r) : "f"(a), "f"(b)); return r;
}
__device__ __forceinline__ void unpack2(ull v, float& a, float& b)
{
    asm("mov.b64 {%0, %1}, %2;" : "=f"(a), "=f"(b) : "l"(v));
}
__device__ __forceinline__ void fma2(ull& acc, ull a, ull b)
{
    asm("fma.rn.f32x2 %0, %1, %2, %0;" : "+l"(acc) : "l"(a), "l"(b));
}
__device__ __forceinline__ ull add2(ull a, ull b)
{
    ull r; asm("add.rn.f32x2 %0, %1, %2;" : "=l"(r) : "l"(a), "l"(b)); return r;
}

// ---------------------------------------------------------------------------
// Kernel 1: xproj = x @ Wx + b  (out doubles as xproj buffer)
// ---------------------------------------------------------------------------
__global__ void __launch_bounds__(256) xproj_kernel(
    const float* __restrict__ x,
    const float* __restrict__ W,     // full (IN+H, H); Wx = rows [0,512)
    const float* __restrict__ bias,
    float* __restrict__ out)
{
    __shared__ float As[16][64];     // [k][m]
    __shared__ float Bs[16][64];     // [k][n]

    const int tid  = threadIdx.x;
    const int row0 = blockIdx.y * 64;
    const int col0 = blockIdx.x * 64;

    const int ty = tid >> 4;               // 0..15
    const int tx = tid & 15;               // 0..15

    const int lmA = tid >> 2;              // 0..63
    const int lkA = (tid & 3) << 2;        // 0,4,8,12
    const int lkB = tid >> 4;              // 0..15
    const int lnB = (tid & 15) << 2;       // 0..60

    ull acc01[4], acc23[4];
#pragma unroll
    for (int i = 0; i < 4; ++i) { acc01[i] = 0ULL; acc23[i] = 0ULL; }

    const float* xg = x + (size_t)(row0 + lmA) * IN_DIM + lkA;

    for (int k0 = 0; k0 < IN_DIM; k0 += 16) {
        float4 av = *(const float4*)(xg + k0);
        As[lkA + 0][lmA] = av.x;
        As[lkA + 1][lmA] = av.y;
        As[lkA + 2][lmA] = av.z;
        As[lkA + 3][lmA] = av.w;

        float4 bv = *(const float4*)(W + (size_t)(k0 + lkB) * H_DIM + col0 + lnB);
        *(float4*)&Bs[lkB][lnB] = bv;

        __syncthreads();
#pragma unroll
        for (int k = 0; k < 16; ++k) {
            float4 a = *(const float4*)&As[k][ty << 2];
            ulonglong2 b = *(const ulonglong2*)&Bs[k][tx << 2];
            ull ax = pack2(a.x, a.x);
            ull ay = pack2(a.y, a.y);
            ull az = pack2(a.z, a.z);
            ull aw = pack2(a.w, a.w);
            fma2(acc01[0], ax, b.x); fma2(acc23[0], ax, b.y);
            fma2(acc01[1], ay, b.x); fma2(acc23[1], ay, b.y);
            fma2(acc01[2], az, b.x); fma2(acc23[2], az, b.y);
            fma2(acc01[3], aw, b.x); fma2(acc23[3], aw, b.y);
        }
        __syncthreads();
    }

    float4 bb = *(const float4*)(bias + col0 + (tx << 2));
#pragma unroll
    for (int i = 0; i < 4; ++i) {
        float s0, s1, s2, s3;
        unpack2(acc01[i], s0, s1);
        unpack2(acc23[i], s2, s3);
        float4 o;
        o.x = s0 + bb.x;
        o.y = s1 + bb.y;
        o.z = s2 + bb.z;
        o.w = s3 + bb.w;
        *(float4*)(out + (size_t)(row0 + (ty << 2) + i) * H_DIM + col0 + (tx << 2)) = o;
    }
}

// ---------------------------------------------------------------------------
// Scan kernel helpers
// ---------------------------------------------------------------------------
__device__ __forceinline__ void cp_async16(float* sdst, const float* gsrc)
{
    unsigned sa = (unsigned)__cvta_generic_to_shared(sdst);
    asm volatile("cp.async.cg.shared.global [%0], [%1], 16;\n" :: "r"(sa), "l"(gsrc));
}

__device__ __forceinline__ void stage_chunk(const float* gsrc, float* sdst, int tid)
{
    // KCHUNK*BATCH = 16384 floats = 4096 float4s; 256 threads * 16 each
#pragma unroll
    for (int i = 0; i < 16; ++i) {
        int idx = tid + i * SCAN_THREADS;
        cp_async16(sdst + idx * 4, gsrc + idx * 4);
    }
}

// Counter+epoch barrier: RMWs on g_count never contend with the read-polls,
// which target only g_epoch.
__device__ __forceinline__ void grid_barrier()
{
    __syncthreads();
    if (threadIdx.x == 0) {
        __threadfence();
        ull old = atomicAdd(&g_count, 1ULL);
        ull target = (old / NCTA + 1ULL) * (ull)NCTA;
        if (old + 1ULL == target) {
            asm volatile("st.release.gpu.global.u64 [%0], %1;" :: "l"(&g_epoch), "l"(target));
        } else {
            ull cur;
            do {
                asm volatile("ld.acquire.gpu.global.u64 %0, [%1];" : "=l"(cur) : "l"(&g_epoch));
            } while (cur < target);
        }
    }
    __syncthreads();
}

// ---------------------------------------------------------------------------
// Kernel 2: persistent recurrent scan.
// 128 CTAs x 256 threads (8 warps, 2/SMSP). CTA owns 8 output columns.
// Microtile: each thread computes 4 rows x 4 cols (8 f32x2 accumulators).
// Warp layout: lane = rg(0..15) + 16*cg(0..1); thread cols = cg*4..cg*4+3,
// rows = rg*4..rg*4+3. Warp w handles k-subslice [w*32, w*32+32) of every
// 256-k chunk. Per 2-k iter: 2 h LDS.128 + 4 w LDS.128 + 16 FFMA2
// -> 4x less crossbar traffic per FLOP than the 4x1 microtile.
// Weights pre-packed (w,w) in smem [c][k] (64KB); h double-buffered (2x64KB).
// 7 warps' partials reduced through smem (aliases hbuf0); warp 0 epilogue.
// ---------------------------------------------------------------------------
__global__ void __launch_bounds__(SCAN_THREADS) scan_kernel(
    const float* __restrict__ hinit,  // initial h (B,H)
    const float* __restrict__ W,      // Wh = rows [512, 1536)
    float* __restrict__ out)
{
    extern __shared__ float smem[];
    ull*   wpk   = (ull*)smem;                          // 8 x 1030 ull = 65920 B
    float* hbuf0 = smem + 2 * 8 * WPK_PITCH;            // [256][64] floats (64 KB)
    float* hbuf1 = hbuf0 + KCHUNK * BATCH;              // (64 KB)
    ulonglong2* red = (ulonglong2*)hbuf0;               // 7*32*4 ull2, reused

    const int tid  = threadIdx.x;
    const int wid  = tid >> 5;                // warp 0..7
    const int lane = tid & 31;
    const int rg   = lane & 15;               // row group: rows rg*4..rg*4+3
    const int cg   = lane >> 4;               // col group: cols cg*4..cg*4+3
    const int col0 = blockIdx.x * COLS_PER_CTA;
    const int c0   = cg * 4;
    const int r0   = rg * 4;

    // Prologue A: transpose my 8 columns of initial h into g_ht[0]
#pragma unroll
    for (int i = tid; i < COLS_PER_CTA * BATCH; i += SCAN_THREADS) {
        int cc = i >> 6;
        int r  = i & 63;
        g_ht[0][(col0 + cc) * BATCH + r] = hinit[(size_t)r * H_DIM + col0 + cc];
    }

    // Prologue B: pre-pack resident Wh slice: wpk[cc][k] = (w, w)
    for (int i = tid; i < H_DIM * COLS_PER_CTA; i += SCAN_THREADS) {
        int cc = i >> 10;
        int k  = i & 1023;
        float w = W[(size_t)(IN_DIM + k) * H_DIM + col0 + cc];
        wpk[cc * WPK_PITCH + k] = pack2(w, w);
    }

    grid_barrier();   // all transposes visible before step-0 staging

    // per-thread weight row pointers (4 cols), k-base = warp subslice
    const ull* wp0 = wpk + (c0 + 0) * WPK_PITCH + wid * KSLICE;
    const ull* wp1 = wpk + (c0 + 1) * WPK_PITCH + wid * KSLICE;
    const ull* wp2 = wpk + (c0 + 2) * WPK_PITCH + wid * KSLICE;
    const ull* wp3 = wpk + (c0 + 3) * WPK_PITCH + wid * KSLICE;

    // warp-0 epilogue offsets
    const size_t eo = (size_t)r0 * H_DIM + col0 + c0;

    // prefetch xp for step 0 (warp 0 only)
    float xp[4][4];
    if (wid == 0) {
#pragma unroll
        for (int i = 0; i < 4; ++i)
            *(float4*)xp[i] = *(const float4*)(out + eo + (size_t)i * H_DIM);
    }

    for (int t = 0; t < T_STEPS; ++t) {
        const float* gh  = g_ht[t & 1];
        float*       ghn = g_ht[(t + 1) & 1];
        float*       outt = out + (size_t)t * BATCH * H_DIM;

        ull acc[2][4];
#pragma unroll
        for (int j = 0; j < 4; ++j) { acc[0][j] = 0ULL; acc[1][j] = 0ULL; }

        // stage chunk 0
        stage_chunk(gh, hbuf0, tid);
        asm volatile("cp.async.commit_group;\n" ::: "memory");

#pragma unroll
        for (int kc = 0; kc < NCHUNKS; ++kc) {
            asm volatile("cp.async.wait_group 0;\n" ::: "memory");
            __syncthreads();
            if (kc + 1 < NCHUNKS) {
                float* nbuf = ((kc + 1) & 1) ? hbuf1 : hbuf0;
                stage_chunk(gh + (size_t)(kc + 1) * KCHUNK * BATCH, nbuf, tid);
                asm volatile("cp.async.commit_group;\n" ::: "memory");
            }

            const float* buf = (kc & 1) ? hbuf1 : hbuf0;
            const float* hb  = buf + wid * KSLICE * BATCH + r0;  // my subslice
            const int kb = kc * KCHUNK;                          // weight k offset
#pragma unroll 8
            for (int kk = 0; kk < KSLICE; kk += 2) {
                const float* hp = hb + kk * BATCH;
                ulonglong2 hA = *(const ulonglong2*)(hp);          // rows r0..r0+3, k
                ulonglong2 hB = *(const ulonglong2*)(hp + BATCH);  // k+1
                ulonglong2 w0 = *(const ulonglong2*)(wp0 + kb + kk);
                ulonglong2 w1 = *(const ulonglong2*)(wp1 + kb + kk);
                ulonglong2 w2 = *(const ulonglong2*)(wp2 + kb + kk);
                ulonglong2 w3 = *(const ulonglong2*)(wp3 + kb + kk);
                fma2(acc[0][0], hA.x, w0.x); fma2(acc[1][0], hA.y, w0.x);
                fma2(acc[0][1], hA.x, w1.x); fma2(acc[1][1], hA.y, w1.x);
                fma2(acc[0][2], hA.x, w2.x); fma2(acc[1][2], hA.y, w2.x);
                fma2(acc[0][3], hA.x, w3.x); fma2(acc[1][3], hA.y, w3.x);
                fma2(acc[0][0], hB.x, w0.y); fma2(acc[1][0], hB.y, w0.y);
                fma2(acc[0][1], hB.x, w1.y); fma2(acc[1][1], hB.y, w1.y);
                fma2(acc[0][2], hB.x, w2.y); fma2(acc[1][2], hB.y, w2.y);
                fma2(acc[0][3], hB.x, w3.y); fma2(acc[1][3], hB.y, w3.y);
            }
        }

        // partial reduction: warps 1..7 store, warp 0 accumulates
        if (wid != 0) {
            ulonglong2* dst = red + ((wid - 1) * 32 + lane) * 4;
            dst[0] = make_ulonglong2(acc[0][0], acc[1][0]);
            dst[1] = make_ulonglong2(acc[0][1], acc[1][1]);
            dst[2] = make_ulonglong2(acc[0][2], acc[1][2]);
            dst[3] = make_ulonglong2(acc[0][3], acc[1][3]);
        }
        __syncthreads();

        if (wid == 0) {
#pragma unroll
            for (int s = 0; s < 7; ++s) {
                const ulonglong2* src = red + (s * 32 + lane) * 4;
#pragma unroll
                for (int j = 0; j < 4; ++j) {
                    ulonglong2 p = src[j];
                    acc[0][j] = add2(acc[0][j], p.x);
                    acc[1][j] = add2(acc[1][j], p.y);
                }
            }

            float v[4][4];
#pragma unroll
            for (int j = 0; j < 4; ++j) {
                unpack2(acc[0][j], v[0][j], v[1][j]);
                unpack2(acc[1][j], v[2][j], v[3][j]);
            }
#pragma unroll
            for (int i = 0; i < 4; ++i)
#pragma unroll
                for (int j = 0; j < 4; ++j)
                    v[i][j] = tanhf(v[i][j] + xp[i][j]);

            // write hidden state rows (STG.128 each)
#pragma unroll
            for (int i = 0; i < 4; ++i)
                *(float4*)(outt + eo + (size_t)i * H_DIM) =
                    make_float4(v[i][0], v[i][1], v[i][2], v[i][3]);

            // transposed copy for next step's staging
#pragma unroll
            for (int j = 0; j < 4; ++j)
                *(float4*)&ghn[(col0 + c0 + j) * BATCH + r0] =
                    make_float4(v[0][j], v[1][j], v[2][j], v[3][j]);

            // prefetch next step's xp; latency hides under grid barrier
            if (t + 1 < T_STEPS) {
                const float* outn = outt + BATCH * H_DIM;
#pragma unroll
                for (int i = 0; i < 4; ++i)
                    *(float4*)xp[i] = *(const float4*)(outn + eo + (size_t)i * H_DIM);
            }
        }

        grid_barrier();
    }
}

// ---------------------------------------------------------------------------
extern "C" void kernel_launch(void* const* d_in, const int* in_sizes, int n_in,
                              void* d_out, int out_size)
{
    (void)in_sizes; (void)n_in; (void)out_size;
    const float* x = (const float*)d_in[0];
    const float* h = (const float*)d_in[1];
    const float* W = (const float*)d_in[2];
    const float* b = (const float*)d_in[3];
    float* out = (float*)d_out;

    // 1) xproj = x @ Wx + b  -> out
    dim3 grid_x(H_DIM / 64, (T_STEPS * BATCH) / 64);
    xproj_kernel<<<grid_x, 256>>>(x, W, b, out);

    // 2) persistent recurrent scan (includes h transpose prologue)
    const size_t smem_bytes = (2 * 8 * WPK_PITCH + 2 * KCHUNK * BATCH) * sizeof(float);
    static int smem_set = 0;
    if (!smem_set) {
        cudaFuncSetAttribute(scan_kernel, cudaFuncAttributeMaxDynamicSharedMemorySize,
                             (int)smem_bytes);
        smem_set = 1;
    }
    scan_kernel<<<NCTA, SCAN_THREADS, smem_bytes>>>(h, W, out);
}

// round 6
// speedup vs baseline: 2.1903x; 1.0749x over previous
#include <cuda_runtime.h>
#include <math.h>
#include <stdint.h>

typedef unsigned long long ull;

#define T_STEPS 1024
#define BATCH   64
#define IN_DIM  512
#define H_DIM   1024

#define NCTA         128
#define SCAN_THREADS 512
#define NWARPS       16
#define COLS_PER_CTA 8          // 128 CTAs * 8 cols = 1024
#define KCHUNK       256        // k-chunk staged in smem per double-buffer slot
#define NCHUNKS      (H_DIM / KCHUNK)   // 4
#define KSLICE       16         // k per warp per chunk (16 warps * 16 = 256)
#define WPK_PITCH    1030       // ull pitch per column (bank-stagger)

// Transposed hidden state, double-buffered: g_ht[p][col*BATCH + row]
__device__ float g_ht[2][H_DIM * BATCH];
// Grid barrier: monotonic arrival counter + separately-polled epoch word
__device__ ull g_count = 0ULL;
__device__ ull g_epoch = 0ULL;

// ---------------------------------------------------------------------------
// packed f32x2 helpers (Blackwell sm_103a)
// ---------------------------------------------------------------------------
__device__ __forceinline__ ull pack2(float a, float b)
{
    ull r; asm("mov.b64 %0, {%1, %2};" : "=l"(r) : "f"(a), "f"(b)); return r;
}
__device__ __forceinline__ void unpack2(ull v, float& a, float& b)
{
    asm("mov.b64 {%0, %1}, %2;" : "=f"(a), "=f"(b) : "l"(v));
}
__device__ __forceinline__ void fma2(ull& acc, ull a, ull b)
{
    asm("fma.rn.f32x2 %0, %1, %2, %0;" : "+l"(acc) : "l"(a), "l"(b));
}
__device__ __forceinline__ ull add2(ull a, ull b)
{
    ull r; asm("add.rn.f32x2 %0, %1, %2;" : "=l"(r) : "l"(a), "l"(b)); return r;
}

// ---------------------------------------------------------------------------
// Kernel 1: xproj = x @ Wx + b  (out doubles as xproj buffer)
// ---------------------------------------------------------------------------
__global__ void __launch_bounds__(256) xproj_kernel(
    const float* __restrict__ x,
    const float* __restrict__ W,     // full (IN+H, H); Wx = rows [0,512)
    const float* __restrict__ bias,
    float* __restrict__ out)
{
    __shared__ float As[16][64];     // [k][m]
    __shared__ float Bs[16][64];     // [k][n]

    const int tid  = threadIdx.x;
    const int row0 = blockIdx.y * 64;
    const int col0 = blockIdx.x * 64;

    const int ty = tid >> 4;               // 0..15
    const int tx = tid & 15;               // 0..15

    const int lmA = tid >> 2;              // 0..63
    const int lkA = (tid & 3) << 2;        // 0,4,8,12
    const int lkB = tid >> 4;              // 0..15
    const int lnB = (tid & 15) << 2;       // 0..60

    ull acc01[4], acc23[4];
#pragma unroll
    for (int i = 0; i < 4; ++i) { acc01[i] = 0ULL; acc23[i] = 0ULL; }

    const float* xg = x + (size_t)(row0 + lmA) * IN_DIM + lkA;

    for (int k0 = 0; k0 < IN_DIM; k0 += 16) {
        float4 av = *(const float4*)(xg + k0);
        As[lkA + 0][lmA] = av.x;
        As[lkA + 1][lmA] = av.y;
        As[lkA + 2][lmA] = av.z;
        As[lkA + 3][lmA] = av.w;

        float4 bv = *(const float4*)(W + (size_t)(k0 + lkB) * H_DIM + col0 + lnB);
        *(float4*)&Bs[lkB][lnB] = bv;

        __syncthreads();
#pragma unroll
        for (int k = 0; k < 16; ++k) {
            float4 a = *(const float4*)&As[k][ty << 2];
            ulonglong2 b = *(const ulonglong2*)&Bs[k][tx << 2];
            ull ax = pack2(a.x, a.x);
            ull ay = pack2(a.y, a.y);
            ull az = pack2(a.z, a.z);
            ull aw = pack2(a.w, a.w);
            fma2(acc01[0], ax, b.x); fma2(acc23[0], ax, b.y);
            fma2(acc01[1], ay, b.x); fma2(acc23[1], ay, b.y);
            fma2(acc01[2], az, b.x); fma2(acc23[2], az, b.y);
            fma2(acc01[3], aw, b.x); fma2(acc23[3], aw, b.y);
        }
        __syncthreads();
    }

    float4 bb = *(const float4*)(bias + col0 + (tx << 2));
#pragma unroll
    for (int i = 0; i < 4; ++i) {
        float s0, s1, s2, s3;
        unpack2(acc01[i], s0, s1);
        unpack2(acc23[i], s2, s3);
        float4 o;
        o.x = s0 + bb.x;
        o.y = s1 + bb.y;
        o.z = s2 + bb.z;
        o.w = s3 + bb.w;
        *(float4*)(out + (size_t)(row0 + (ty << 2) + i) * H_DIM + col0 + (tx << 2)) = o;
    }
}

// ---------------------------------------------------------------------------
// Scan kernel helpers
// ---------------------------------------------------------------------------
__device__ __forceinline__ void cp_async16(float* sdst, const float* gsrc)
{
    unsigned sa = (unsigned)__cvta_generic_to_shared(sdst);
    asm volatile("cp.async.cg.shared.global [%0], [%1], 16;\n" :: "r"(sa), "l"(gsrc));
}

__device__ __forceinline__ void stage_chunk(const float* gsrc, float* sdst, int tid)
{
    // KCHUNK*BATCH = 16384 floats = 4096 float4s; 512 threads * 8 each
#pragma unroll
    for (int i = 0; i < 8; ++i) {
        int idx = tid + i * SCAN_THREADS;
        cp_async16(sdst + idx * 4, gsrc + idx * 4);
    }
}

// Counter+epoch barrier: RMWs on g_count never contend with the read-polls,
// which target only g_epoch.
__device__ __forceinline__ void grid_barrier()
{
    __syncthreads();
    if (threadIdx.x == 0) {
        __threadfence();
        ull old = atomicAdd(&g_count, 1ULL);
        ull target = (old / NCTA + 1ULL) * (ull)NCTA;
        if (old + 1ULL == target) {
            asm volatile("st.release.gpu.global.u64 [%0], %1;" :: "l"(&g_epoch), "l"(target));
        } else {
            ull cur;
            do {
                asm volatile("ld.acquire.gpu.global.u64 %0, [%1];" : "=l"(cur) : "l"(&g_epoch));
            } while (cur < target);
        }
    }
    __syncthreads();
}

// ---------------------------------------------------------------------------
// Kernel 2: persistent recurrent scan.
// 128 CTAs x 512 threads (16 warps, 4/SMSP). CTA owns 8 output columns.
// Microtile: 4 rows x 4 cols per thread (lane = rg(0..15) + 16*cg(0..1)).
// Warp w handles k-subslice [w*16, w*16+16) of each 256-k chunk.
// Partials stored red[j][s][lane] (lane-contiguous -> 4-wf STS/LDS);
// epilogue distributed: warp e (0..3) reduces + tanh + writes column j=e.
// ---------------------------------------------------------------------------
__global__ void __launch_bounds__(SCAN_THREADS) scan_kernel(
    const float* __restrict__ hinit,  // initial h (B,H)
    const float* __restrict__ W,      // Wh = rows [512, 1536)
    float* __restrict__ out)
{
    extern __shared__ float smem[];
    ull*   wpk   = (ull*)smem;                          // 8 x 1030 ull = 65920 B
    float* hbuf0 = smem + 2 * 8 * WPK_PITCH;            // [256][64] floats (64 KB)
    float* hbuf1 = hbuf0 + KCHUNK * BATCH;              // (64 KB)
    ulonglong2* red = (ulonglong2*)hbuf0;               // [4][16][32] ull2 = 32KB, reused

    const int tid  = threadIdx.x;
    const int wid  = tid >> 5;                // warp 0..15
    const int lane = tid & 31;
    const int rg   = lane & 15;               // rows rg*4..rg*4+3
    const int cg   = lane >> 4;               // cols cg*4..cg*4+3
    const int col0 = blockIdx.x * COLS_PER_CTA;
    const int c0   = cg * 4;
    const int r0   = rg * 4;

    // Prologue A: transpose my 8 columns of initial h into g_ht[0]
    {
        int cc = tid >> 6;        // 0..7
        int r  = tid & 63;        // 0..63
        g_ht[0][(col0 + cc) * BATCH + r] = hinit[(size_t)r * H_DIM + col0 + cc];
    }

    // Prologue B: pre-pack resident Wh slice: wpk[cc][k] = (w, w)
    for (int i = tid; i < H_DIM * COLS_PER_CTA; i += SCAN_THREADS) {
        int cc = i >> 10;
        int k  = i & 1023;
        float w = W[(size_t)(IN_DIM + k) * H_DIM + col0 + cc];
        wpk[cc * WPK_PITCH + k] = pack2(w, w);
    }

    grid_barrier();   // all transposes visible before step-0 staging

    // per-thread weight row pointers (4 cols), k-base = warp subslice
    const ull* wp0 = wpk + (c0 + 0) * WPK_PITCH + wid * KSLICE;
    const ull* wp1 = wpk + (c0 + 1) * WPK_PITCH + wid * KSLICE;
    const ull* wp2 = wpk + (c0 + 2) * WPK_PITCH + wid * KSLICE;
    const ull* wp3 = wpk + (c0 + 3) * WPK_PITCH + wid * KSLICE;

    // epilogue thread's output column and row offsets (warps 0..3 only)
    const int  colE = col0 + c0 + wid;                  // valid when wid<4
    const size_t eo0 = (size_t)(r0 + 0) * H_DIM + colE;
    const size_t eo1 = (size_t)(r0 + 1) * H_DIM + colE;
    const size_t eo2 = (size_t)(r0 + 2) * H_DIM + colE;
    const size_t eo3 = (size_t)(r0 + 3) * H_DIM + colE;

    // prefetch xp for step 0 (epilogue warps)
    float xp0 = 0.f, xp1 = 0.f, xp2 = 0.f, xp3 = 0.f;
    if (wid < 4) {
        xp0 = out[eo0]; xp1 = out[eo1]; xp2 = out[eo2]; xp3 = out[eo3];
    }

    for (int t = 0; t < T_STEPS; ++t) {
        const float* gh  = g_ht[t & 1];
        float*       ghn = g_ht[(t + 1) & 1];
        float*       outt = out + (size_t)t * BATCH * H_DIM;

        ull acc[2][4];
#pragma unroll
        for (int j = 0; j < 4; ++j) { acc[0][j] = 0ULL; acc[1][j] = 0ULL; }

        // stage chunk 0
        stage_chunk(gh, hbuf0, tid);
        asm volatile("cp.async.commit_group;\n" ::: "memory");

#pragma unroll
        for (int kc = 0; kc < NCHUNKS; ++kc) {
            asm volatile("cp.async.wait_group 0;\n" ::: "memory");
            __syncthreads();
            if (kc + 1 < NCHUNKS) {
                float* nbuf = ((kc + 1) & 1) ? hbuf1 : hbuf0;
                stage_chunk(gh + (size_t)(kc + 1) * KCHUNK * BATCH, nbuf, tid);
                asm volatile("cp.async.commit_group;\n" ::: "memory");
            }

            const float* buf = (kc & 1) ? hbuf1 : hbuf0;
            const float* hb  = buf + wid * KSLICE * BATCH + r0;  // my subslice
            const int kb = kc * KCHUNK;
#pragma unroll 8
            for (int kk = 0; kk < KSLICE; kk += 2) {
                const float* hp = hb + kk * BATCH;
                ulonglong2 hA = *(const ulonglong2*)(hp);          // rows r0..r0+3, k
                ulonglong2 hB = *(const ulonglong2*)(hp + BATCH);  // k+1
                ulonglong2 w0 = *(const ulonglong2*)(wp0 + kb + kk);
                ulonglong2 w1 = *(const ulonglong2*)(wp1 + kb + kk);
                ulonglong2 w2 = *(const ulonglong2*)(wp2 + kb + kk);
                ulonglong2 w3 = *(const ulonglong2*)(wp3 + kb + kk);
                fma2(acc[0][0], hA.x, w0.x); fma2(acc[1][0], hA.y, w0.x);
                fma2(acc[0][1], hA.x, w1.x); fma2(acc[1][1], hA.y, w1.x);
                fma2(acc[0][2], hA.x, w2.x); fma2(acc[1][2], hA.y, w2.x);
                fma2(acc[0][3], hA.x, w3.x); fma2(acc[1][3], hA.y, w3.x);
                fma2(acc[0][0], hB.x, w0.y); fma2(acc[1][0], hB.y, w0.y);
                fma2(acc[0][1], hB.x, w1.y); fma2(acc[1][1], hB.y, w1.y);
                fma2(acc[0][2], hB.x, w2.y); fma2(acc[1][2], hB.y, w2.y);
                fma2(acc[0][3], hB.x, w3.y); fma2(acc[1][3], hB.y, w3.y);
            }
        }

        // store partials: red[j][s=wid][lane], lane-contiguous (4 wf per STS)
#pragma unroll
        for (int j = 0; j < 4; ++j)
            red[(j * NWARPS + wid) * 32 + lane] = make_ulonglong2(acc[0][j], acc[1][j]);
        __syncthreads();

        // distributed epilogue: warp e reduces + writes column j=e
        if (wid < 4) {
            ull s01 = 0ULL, s23 = 0ULL;
#pragma unroll
            for (int s = 0; s < NWARPS; ++s) {
                ulonglong2 p = red[(wid * NWARPS + s) * 32 + lane];
                s01 = add2(s01, p.x);
                s23 = add2(s23, p.y);
            }
            float v0, v1, v2, v3;
            unpack2(s01, v0, v1);
            unpack2(s23, v2, v3);
            v0 = tanhf(v0 + xp0);
            v1 = tanhf(v1 + xp1);
            v2 = tanhf(v2 + xp2);
            v3 = tanhf(v3 + xp3);

            // hidden state to output history (column-scattered, small)
            outt[eo0] = v0;
            outt[eo1] = v1;
            outt[eo2] = v2;
            outt[eo3] = v3;

            // transposed copy for next step's staging (coalesced float4)
            *(float4*)&ghn[colE * BATCH + r0] = make_float4(v0, v1, v2, v3);

            // prefetch next step's xp; latency hides under the grid barrier
            if (t + 1 < T_STEPS) {
                const float* outn = outt + BATCH * H_DIM;
                xp0 = outn[eo0]; xp1 = outn[eo1]; xp2 = outn[eo2]; xp3 = outn[eo3];
            }
        }

        grid_barrier();
    }
}

// ---------------------------------------------------------------------------
extern "C" void kernel_launch(void* const* d_in, const int* in_sizes, int n_in,
                              void* d_out, int out_size)
{
    (void)in_sizes; (void)n_in; (void)out_size;
    const float* x = (const float*)d_in[0];
    const float* h = (const float*)d_in[1];
    const float* W = (const float*)d_in[2];
    const float* b = (const float*)d_in[3];
    float* out = (float*)d_out;

    // 1) xproj = x @ Wx + b  -> out
    dim3 grid_x(H_DIM / 64, (T_STEPS * BATCH) / 64);
    xproj_kernel<<<grid_x, 256>>>(x, W, b, out);

    // 2) persistent recurrent scan (includes h transpose prologue)
    const size_t smem_bytes = (2 * 8 * WPK_PITCH + 2 * KCHUNK * BATCH) * sizeof(float);
    static int smem_set = 0;
    if (!smem_set) {
        cudaFuncSetAttribute(scan_kernel, cudaFuncAttributeMaxDynamicSharedMemorySize,
                             (int)smem_bytes);
        smem_set = 1;
    }
    scan_kernel<<<NCTA, SCAN_THREADS, smem_bytes>>>(h, W, out);
}